// round 2
// baseline (speedup 1.0000x reference)
#include <cuda_runtime.h>

// ---------------- problem constants ----------------
#define BB   4
#define HH   8
#define NN   2048
#define BHN  (BB*HH)          // 32
#define DHD  16               // head dim == v head dim
#define MROWS (BB*NN)         // 8192

typedef unsigned long long u64;

// ---------------- scratch (static device, no allocs) ----------------
__device__ float g_qs[BHN * NN * DHD];      // [bh][n][16], log2e*scaling folded in
__device__ float g_ks[BHN * NN * DHD];      // [bh][n][16]
__device__ float g_vs[BHN * NN * DHD];      // [bh][n][16]
__device__ float g_ctx[MROWS * 128];        // [b*N+n][h*16+e]

// ---------------- helpers ----------------
__device__ __forceinline__ float ex2f_fast(float x) {
    float y;
    asm("ex2.approx.ftz.f32 %0, %1;" : "=f"(y) : "f"(x));
    return y;
}
// packed fp32x2 ops (exact fp32 per lane, 2x FFMA throughput)
__device__ __forceinline__ u64 fmul2(u64 a, u64 b) {
    u64 d; asm("mul.rn.f32x2 %0, %1, %2;" : "=l"(d) : "l"(a), "l"(b)); return d;
}
__device__ __forceinline__ u64 ffma2(u64 a, u64 b, u64 c) {
    u64 d; asm("fma.rn.f32x2 %0, %1, %2, %3;" : "=l"(d) : "l"(a), "l"(b), "l"(c)); return d;
}
__device__ __forceinline__ u64 pack2(float lo, float hi) {
    u64 d; asm("mov.b64 %0, {%1, %2};" : "=l"(d) : "f"(lo), "f"(hi)); return d;
}
__device__ __forceinline__ float red2(u64 a) {
    float lo, hi; asm("mov.b64 {%0, %1}, %2;" : "=f"(lo), "=f"(hi) : "l"(a));
    return lo + hi;
}
__device__ __forceinline__ float dot4acc(float4 a, float4 b, float t) {
    t = fmaf(a.x, b.x, t); t = fmaf(a.y, b.y, t);
    t = fmaf(a.z, b.z, t); t = fmaf(a.w, b.w, t);
    return t;
}

// ---------------- Q/K projection ----------------
__global__ void __launch_bounds__(128) projqk_kernel(
    const float* __restrict__ Aq, const float* __restrict__ Ak,
    const float* __restrict__ Wq, const float* __restrict__ Wk,
    const float* __restrict__ bq, const float* __restrict__ bk,
    float alpha_q)
{
    const int TM = 32;
    __shared__ float As[TM][128];
    __shared__ float Ws[32][129];

    const bool is_k = (blockIdx.y != 0);
    const float* A    = is_k ? Ak : Aq;
    const float* W    = is_k ? Wk : Wq;
    const float* bias = is_k ? bk : bq;
    float*       outp = is_k ? g_ks : g_qs;
    const float alpha = is_k ? 1.0f : alpha_q;

    const int r0 = blockIdx.x * TM;
    const int c  = threadIdx.x;

    {
        const float4* Ag = (const float4*)(A + (size_t)r0 * 128);
        float4* Asv = (float4*)&As[0][0];
        #pragma unroll
        for (int i = 0; i < 8; i++) Asv[c + 128 * i] = Ag[c + 128 * i];
    }

    float acc[TM];
    #pragma unroll
    for (int r = 0; r < TM; r++) acc[r] = 0.f;

    for (int k0 = 0; k0 < 128; k0 += 32) {
        __syncthreads();
        const float4* wg = (const float4*)(W + c * 128 + k0);
        #pragma unroll
        for (int i = 0; i < 8; i++) {
            float4 w4 = wg[i];
            Ws[i * 4 + 0][c] = w4.x; Ws[i * 4 + 1][c] = w4.y;
            Ws[i * 4 + 2][c] = w4.z; Ws[i * 4 + 3][c] = w4.w;
        }
        __syncthreads();
        #pragma unroll
        for (int kk = 0; kk < 32; kk += 4) {
            const float w0 = Ws[kk + 0][c], w1 = Ws[kk + 1][c];
            const float w2 = Ws[kk + 2][c], w3 = Ws[kk + 3][c];
            #pragma unroll
            for (int r = 0; r < TM; r++) {
                float4 a4 = *(const float4*)&As[r][k0 + kk];
                float t = acc[r];
                t = fmaf(a4.x, w0, t); t = fmaf(a4.y, w1, t);
                t = fmaf(a4.z, w2, t); t = fmaf(a4.w, w3, t);
                acc[r] = t;
            }
        }
    }

    const float bc = bias[c];
    const int h = c >> 4, d = c & 15;
    #pragma unroll
    for (int r = 0; r < TM; r++) {
        const int row = r0 + r;
        const int b = row >> 11, n = row & 2047;
        outp[(((size_t)(b * HH + h) * NN + n) << 4) + d] = (acc[r] + bc) * alpha;
    }
}

// ---------------- V projection ----------------
__global__ void __launch_bounds__(256) projv_kernel(
    const float* __restrict__ value, const float* __restrict__ Wv,
    const float* __restrict__ bv)
{
    const int o = blockIdx.x * 256 + threadIdx.x;
    const int r = o >> 7, c = o & 127;
    const float4* a = (const float4*)(value + ((size_t)r << 4));
    const float4* w = (const float4*)(Wv + ((size_t)c << 4));
    float4 a0 = a[0], a1 = a[1], a2 = a[2], a3 = a[3];
    float4 w0 = w[0], w1 = w[1], w2 = w[2], w3 = w[3];
    float t = bv[c];
    t = dot4acc(a0, w0, t); t = dot4acc(a1, w1, t);
    t = dot4acc(a2, w2, t); t = dot4acc(a3, w3, t);
    const int b = r >> 11, n = r & 2047, h = c >> 4, d = c & 15;
    g_vs[(((size_t)(b * HH + h) * NN + n) << 4) + d] = t;
}

// ---------------- fused flash attention (fp32, f32x2 packed, 2 q-rows/thread) ----------------
// grid: 256 CTAs = 32 (b,h) x 8 q-tiles of 256 rows; 128 threads; thread t owns
// rows t and t+128 of the tile. Softmax in log2 domain (alpha*log2e folded into q).
__global__ void __launch_bounds__(128) attn_kernel()
{
    const int TK = 128;
    const int bh  = blockIdx.x >> 3;
    const int rt  = blockIdx.x & 7;
    const int tid = threadIdx.x;
    const int row0 = rt * 256 + tid;          // second row is row0 + 128

    // q rows as 8 packed f32x2 each
    const u64* q0p = (const u64*)(g_qs + (((size_t)bh * NN + row0) << 4));
    const u64* q1p = q0p + (128 << 3);        // +128 rows * 8 u64
    u64 q0[8], q1[8];
    #pragma unroll
    for (int i = 0; i < 8; i++) { q0[i] = q0p[i]; q1[i] = q1p[i]; }

    __shared__ __align__(16) u64 Ks[TK * 8];  // 8KB: 128 rows x 16 floats
    __shared__ __align__(16) u64 Vs[TK * 8];  // 8KB

    float m0 = -1e30f, l0 = 0.f, m1 = -1e30f, l1 = 0.f;
    u64 o0[8], o1[8];
    const u64 zz = pack2(0.f, 0.f);
    #pragma unroll
    for (int i = 0; i < 8; i++) { o0[i] = zz; o1[i] = zz; }

    const ulonglong2* Kg = (const ulonglong2*)(g_ks + ((size_t)bh * NN << 4));
    const ulonglong2* Vg = (const ulonglong2*)(g_vs + ((size_t)bh * NN << 4));

    for (int t0 = 0; t0 < NN; t0 += TK) {
        __syncthreads();
        ulonglong2* Ks2 = (ulonglong2*)Ks;
        ulonglong2* Vs2 = (ulonglong2*)Vs;
        #pragma unroll
        for (int i = 0; i < 4; i++) {
            Ks2[tid + 128 * i] = Kg[t0 * 4 + tid + 128 * i];
            Vs2[tid + 128 * i] = Vg[t0 * 4 + tid + 128 * i];
        }
        __syncthreads();

        #pragma unroll 1
        for (int jc = 0; jc < TK; jc += 8) {
            float s0[8], s1[8];
            float cm0 = -1e30f, cm1 = -1e30f;
            // scores for 8 keys x 2 q-rows
            #pragma unroll
            for (int jj = 0; jj < 8; jj++) {
                const u64* kr = &Ks[(jc + jj) * 8];
                u64 k0 = kr[0], k1 = kr[1], k2 = kr[2], k3 = kr[3];
                u64 k4 = kr[4], k5 = kr[5], k6 = kr[6], k7 = kr[7];
                u64 a = fmul2(q0[0], k0);
                a = ffma2(q0[1], k1, a); a = ffma2(q0[2], k2, a);
                a = ffma2(q0[3], k3, a); a = ffma2(q0[4], k4, a);
                a = ffma2(q0[5], k5, a); a = ffma2(q0[6], k6, a);
                a = ffma2(q0[7], k7, a);
                u64 b = fmul2(q1[0], k0);
                b = ffma2(q1[1], k1, b); b = ffma2(q1[2], k2, b);
                b = ffma2(q1[3], k3, b); b = ffma2(q1[4], k4, b);
                b = ffma2(q1[5], k5, b); b = ffma2(q1[6], k6, b);
                b = ffma2(q1[7], k7, b);
                s0[jj] = red2(a); cm0 = fmaxf(cm0, s0[jj]);
                s1[jj] = red2(b); cm1 = fmaxf(cm1, s1[jj]);
            }
            // running-max correction (log2 domain)
            {
                const float mn = fmaxf(m0, cm0);
                const float c = ex2f_fast(m0 - mn);
                m0 = mn; l0 *= c;
                const u64 c2 = pack2(c, c);
                #pragma unroll
                for (int i = 0; i < 8; i++) o0[i] = fmul2(o0[i], c2);
            }
            {
                const float mn = fmaxf(m1, cm1);
                const float c = ex2f_fast(m1 - mn);
                m1 = mn; l1 *= c;
                const u64 c2 = pack2(c, c);
                #pragma unroll
                for (int i = 0; i < 8; i++) o1[i] = fmul2(o1[i], c2);
            }
            // exp + PV accumulate
            #pragma unroll
            for (int jj = 0; jj < 8; jj++) {
                const u64* vr = &Vs[(jc + jj) * 8];
                const float p0 = ex2f_fast(s0[jj] - m0); l0 += p0;
                const float p1 = ex2f_fast(s1[jj] - m1); l1 += p1;
                const u64 p02 = pack2(p0, p0);
                const u64 p12 = pack2(p1, p1);
                #pragma unroll
                for (int i = 0; i < 8; i++) {
                    const u64 v = vr[i];
                    o0[i] = ffma2(p02, v, o0[i]);
                    o1[i] = ffma2(p12, v, o1[i]);
                }
            }
        }
    }

    const float inv0 = 1.0f / l0;
    const float inv1 = 1.0f / l1;
    const u64 i02 = pack2(inv0, inv0);
    const u64 i12 = pack2(inv1, inv1);
    #pragma unroll
    for (int i = 0; i < 8; i++) { o0[i] = fmul2(o0[i], i02); o1[i] = fmul2(o1[i], i12); }

    const int b = bh >> 3, h = bh & 7;
    u64* op0 = (u64*)g_ctx + (((size_t)(b * NN + row0)) << 6) + h * 8;
    u64* op1 = (u64*)g_ctx + (((size_t)(b * NN + row0 + 128)) << 6) + h * 8;
    #pragma unroll
    for (int i = 0; i < 8; i++) { op0[i] = o0[i]; op1[i] = o1[i]; }
}

// ---------------- output projection: ctx[8192,128] @ Wo[16,128]^T + bo ----------------
__global__ void __launch_bounds__(256) outproj_kernel(
    const float* __restrict__ Wo, const float* __restrict__ bo,
    float* __restrict__ out)
{
    __shared__ float Cs[16][128];
    __shared__ float Ws[16][132];
    const int r0 = blockIdx.x * 16;

    const float4* cg = (const float4*)(g_ctx + ((size_t)r0 << 7));
    float4* csv = (float4*)&Cs[0][0];
    csv[threadIdx.x]       = cg[threadIdx.x];
    csv[threadIdx.x + 256] = cg[threadIdx.x + 256];
    for (int i = threadIdx.x; i < 2048; i += 256) Ws[i >> 7][i & 127] = Wo[i];
    __syncthreads();

    const int r = threadIdx.x >> 4, c = threadIdx.x & 15;
    float acc = bo[c];
    #pragma unroll
    for (int kk = 0; kk < 128; kk += 4) {
        float4 a = *(const float4*)&Cs[r][kk];
        float4 w = *(const float4*)&Ws[c][kk];
        acc = dot4acc(a, w, acc);
    }
    out[((size_t)(r0 + r) << 4) + c] = acc;
}

// ---------------- launcher ----------------
extern "C" void kernel_launch(void* const* d_in, const int* in_sizes, int n_in,
                              void* d_out, int out_size)
{
    const float* query = (const float*)d_in[0];
    const float* key   = (const float*)d_in[1];
    const float* value = (const float*)d_in[2];
    const float* Wq    = (const float*)d_in[3];
    const float* bq    = (const float*)d_in[4];
    const float* Wk    = (const float*)d_in[5];
    const float* bk    = (const float*)d_in[6];
    const float* Wv    = (const float*)d_in[7];
    const float* bv    = (const float*)d_in[8];
    const float* Wo    = (const float*)d_in[9];
    const float* bo    = (const float*)d_in[10];
    float* out = (float*)d_out;

    const float LOG2E = 1.4426950408889634f;
    const float alpha_q = 0.25f * LOG2E;

    dim3 gqk(MROWS / 32, 2);
    projqk_kernel<<<gqk, 128>>>(query, key, Wq, Wk, bq, bk, alpha_q);
    projv_kernel<<<(MROWS * 128) / 256, 256>>>(value, Wv, bv);
    attn_kernel<<<BHN * (NN / 256), 128>>>();
    outproj_kernel<<<MROWS / 16, 256>>>(Wo, bo, out);
}

// round 3
// speedup vs baseline: 1.3376x; 1.3376x over previous
#include <cuda_runtime.h>

// ---------------- problem constants ----------------
#define BB   4
#define HH   8
#define NN   2048
#define BHN  (BB*HH)          // 32
#define DHD  16               // head dim == v head dim
#define MROWS (BB*NN)         // 8192

typedef unsigned long long u64;

// ---------------- scratch (static device, no allocs) ----------------
__device__ float g_qs[BHN * NN * DHD];      // [bh][n][16], log2e*scaling folded in
__device__ float g_ks[BHN * NN * DHD];      // [bh][n][16]
__device__ float g_vs[BHN * NN * DHD];      // [bh][n][16]
__device__ float g_ctx[MROWS * 128];        // [b*N+n][h*16+e]

// ---------------- helpers ----------------
__device__ __forceinline__ float ex2f_fast(float x) {
    float y;
    asm("ex2.approx.ftz.f32 %0, %1;" : "=f"(y) : "f"(x));
    return y;
}
// packed fp32x2 ops (exact fp32 per lane, halves FFMA instruction count)
__device__ __forceinline__ u64 fmul2(u64 a, u64 b) {
    u64 d; asm("mul.rn.f32x2 %0, %1, %2;" : "=l"(d) : "l"(a), "l"(b)); return d;
}
__device__ __forceinline__ u64 ffma2(u64 a, u64 b, u64 c) {
    u64 d; asm("fma.rn.f32x2 %0, %1, %2, %3;" : "=l"(d) : "l"(a), "l"(b), "l"(c)); return d;
}
__device__ __forceinline__ u64 pack2(float lo, float hi) {
    u64 d; asm("mov.b64 %0, {%1, %2};" : "=l"(d) : "f"(lo), "f"(hi)); return d;
}
__device__ __forceinline__ float red2(u64 a) {
    float lo, hi; asm("mov.b64 {%0, %1}, %2;" : "=f"(lo), "=f"(hi) : "l"(a));
    return lo + hi;
}
__device__ __forceinline__ float dot4acc(float4 a, float4 b, float t) {
    t = fmaf(a.x, b.x, t); t = fmaf(a.y, b.y, t);
    t = fmaf(a.z, b.z, t); t = fmaf(a.w, b.w, t);
    return t;
}

// ---------------- Q/K projection ----------------
__global__ void __launch_bounds__(128) projqk_kernel(
    const float* __restrict__ Aq, const float* __restrict__ Ak,
    const float* __restrict__ Wq, const float* __restrict__ Wk,
    const float* __restrict__ bq, const float* __restrict__ bk,
    float alpha_q)
{
    const int TM = 32;
    __shared__ float As[TM][128];
    __shared__ float Ws[32][129];

    const bool is_k = (blockIdx.y != 0);
    const float* A    = is_k ? Ak : Aq;
    const float* W    = is_k ? Wk : Wq;
    const float* bias = is_k ? bk : bq;
    float*       outp = is_k ? g_ks : g_qs;
    const float alpha = is_k ? 1.0f : alpha_q;

    const int r0 = blockIdx.x * TM;
    const int c  = threadIdx.x;

    {
        const float4* Ag = (const float4*)(A + (size_t)r0 * 128);
        float4* Asv = (float4*)&As[0][0];
        #pragma unroll
        for (int i = 0; i < 8; i++) Asv[c + 128 * i] = Ag[c + 128 * i];
    }

    float acc[TM];
    #pragma unroll
    for (int r = 0; r < TM; r++) acc[r] = 0.f;

    for (int k0 = 0; k0 < 128; k0 += 32) {
        __syncthreads();
        const float4* wg = (const float4*)(W + c * 128 + k0);
        #pragma unroll
        for (int i = 0; i < 8; i++) {
            float4 w4 = wg[i];
            Ws[i * 4 + 0][c] = w4.x; Ws[i * 4 + 1][c] = w4.y;
            Ws[i * 4 + 2][c] = w4.z; Ws[i * 4 + 3][c] = w4.w;
        }
        __syncthreads();
        #pragma unroll
        for (int kk = 0; kk < 32; kk += 4) {
            const float w0 = Ws[kk + 0][c], w1 = Ws[kk + 1][c];
            const float w2 = Ws[kk + 2][c], w3 = Ws[kk + 3][c];
            #pragma unroll
            for (int r = 0; r < TM; r++) {
                float4 a4 = *(const float4*)&As[r][k0 + kk];
                float t = acc[r];
                t = fmaf(a4.x, w0, t); t = fmaf(a4.y, w1, t);
                t = fmaf(a4.z, w2, t); t = fmaf(a4.w, w3, t);
                acc[r] = t;
            }
        }
    }

    const float bc = bias[c];
    const int h = c >> 4, d = c & 15;
    #pragma unroll
    for (int r = 0; r < TM; r++) {
        const int row = r0 + r;
        const int b = row >> 11, n = row & 2047;
        outp[(((size_t)(b * HH + h) * NN + n) << 4) + d] = (acc[r] + bc) * alpha;
    }
}

// ---------------- V projection ----------------
__global__ void __launch_bounds__(256) projv_kernel(
    const float* __restrict__ value, const float* __restrict__ Wv,
    const float* __restrict__ bv)
{
    const int o = blockIdx.x * 256 + threadIdx.x;
    const int r = o >> 7, c = o & 127;
    const float4* a = (const float4*)(value + ((size_t)r << 4));
    const float4* w = (const float4*)(Wv + ((size_t)c << 4));
    float4 a0 = a[0], a1 = a[1], a2 = a[2], a3 = a[3];
    float4 w0 = w[0], w1 = w[1], w2 = w[2], w3 = w[3];
    float t = bv[c];
    t = dot4acc(a0, w0, t); t = dot4acc(a1, w1, t);
    t = dot4acc(a2, w2, t); t = dot4acc(a3, w3, t);
    const int b = r >> 11, n = r & 2047, h = c >> 4, d = c & 15;
    g_vs[(((size_t)(b * HH + h) * NN + n) << 4) + d] = t;
}

// ---------------- fused flash attention ----------------
// Round-1 launch shape (512 CTAs x 128 thr, 1 q-row/thread, 3.46 warps/SMSP)
// + f32x2 packed FFMA + LDS.128 staging (ulonglong2 halves feed FFMA2 directly).
__global__ void __launch_bounds__(128) attn_kernel()
{
    const int TK = 128;
    const int bh  = blockIdx.x >> 4;
    const int rt  = blockIdx.x & 15;
    const int tid = threadIdx.x;
    const int row = rt * 128 + tid;

    // q row as 8 packed f32x2
    const u64* qp = (const u64*)(g_qs + (((size_t)bh * NN + row) << 4));
    u64 q[8];
    #pragma unroll
    for (int i = 0; i < 8; i++) q[i] = qp[i];

    __shared__ __align__(16) ulonglong2 Ks[TK * 4];   // 8KB: 128 rows x 16 floats
    __shared__ __align__(16) ulonglong2 Vs[TK * 4];   // 8KB

    float m = -1e30f, l = 0.f;
    u64 o[8];
    const u64 zz = pack2(0.f, 0.f);
    #pragma unroll
    for (int i = 0; i < 8; i++) o[i] = zz;

    const ulonglong2* Kg = (const ulonglong2*)(g_ks + ((size_t)bh * NN << 4));
    const ulonglong2* Vg = (const ulonglong2*)(g_vs + ((size_t)bh * NN << 4));

    for (int t0 = 0; t0 < NN; t0 += TK) {
        __syncthreads();
        #pragma unroll
        for (int i = 0; i < 4; i++) {
            Ks[tid + 128 * i] = Kg[t0 * 4 + tid + 128 * i];
            Vs[tid + 128 * i] = Vg[t0 * 4 + tid + 128 * i];
        }
        __syncthreads();

        #pragma unroll 1
        for (int jc = 0; jc < TK; jc += 16) {
            float s[16];
            float cm = -1e30f;
            // scores: 16 keys, 8 FFMA2 each (4x LDS.128 per key, broadcast)
            #pragma unroll
            for (int jj = 0; jj < 16; jj++) {
                const ulonglong2* kr = &Ks[(jc + jj) * 4];
                ulonglong2 a0 = kr[0], a1 = kr[1], a2 = kr[2], a3 = kr[3];
                u64 acc = fmul2(q[0], a0.x);
                acc = ffma2(q[1], a0.y, acc);
                acc = ffma2(q[2], a1.x, acc);
                acc = ffma2(q[3], a1.y, acc);
                acc = ffma2(q[4], a2.x, acc);
                acc = ffma2(q[5], a2.y, acc);
                acc = ffma2(q[6], a3.x, acc);
                acc = ffma2(q[7], a3.y, acc);
                s[jj] = red2(acc);
                cm = fmaxf(cm, s[jj]);
            }
            // running-max correction (log2 domain)
            {
                const float mn = fmaxf(m, cm);
                const float c = ex2f_fast(m - mn);
                m = mn; l *= c;
                const u64 c2 = pack2(c, c);
                #pragma unroll
                for (int i = 0; i < 8; i++) o[i] = fmul2(o[i], c2);
            }
            // exp + PV accumulate (8 FFMA2 per key)
            #pragma unroll
            for (int jj = 0; jj < 16; jj++) {
                const ulonglong2* vr = &Vs[(jc + jj) * 4];
                const float p = ex2f_fast(s[jj] - m);
                l += p;
                const u64 pp = pack2(p, p);
                ulonglong2 v0 = vr[0], v1 = vr[1], v2 = vr[2], v3 = vr[3];
                o[0] = ffma2(pp, v0.x, o[0]);
                o[1] = ffma2(pp, v0.y, o[1]);
                o[2] = ffma2(pp, v1.x, o[2]);
                o[3] = ffma2(pp, v1.y, o[3]);
                o[4] = ffma2(pp, v2.x, o[4]);
                o[5] = ffma2(pp, v2.y, o[5]);
                o[6] = ffma2(pp, v3.x, o[6]);
                o[7] = ffma2(pp, v3.y, o[7]);
            }
        }
    }

    const float inv = 1.0f / l;
    const u64 i2 = pack2(inv, inv);
    #pragma unroll
    for (int i = 0; i < 8; i++) o[i] = fmul2(o[i], i2);

    const int b = bh >> 3, h = bh & 7;
    u64* op = (u64*)g_ctx + (((size_t)(b * NN + row)) << 6) + h * 8;
    #pragma unroll
    for (int i = 0; i < 8; i++) op[i] = o[i];
}

// ---------------- output projection: ctx[8192,128] @ Wo[16,128]^T + bo ----------------
__global__ void __launch_bounds__(256) outproj_kernel(
    const float* __restrict__ Wo, const float* __restrict__ bo,
    float* __restrict__ out)
{
    __shared__ float Cs[16][128];
    __shared__ float Ws[16][132];
    const int r0 = blockIdx.x * 16;

    const float4* cg = (const float4*)(g_ctx + ((size_t)r0 << 7));
    float4* csv = (float4*)&Cs[0][0];
    csv[threadIdx.x]       = cg[threadIdx.x];
    csv[threadIdx.x + 256] = cg[threadIdx.x + 256];
    for (int i = threadIdx.x; i < 2048; i += 256) Ws[i >> 7][i & 127] = Wo[i];
    __syncthreads();

    const int r = threadIdx.x >> 4, c = threadIdx.x & 15;
    float acc = bo[c];
    #pragma unroll
    for (int kk = 0; kk < 128; kk += 4) {
        float4 a = *(const float4*)&Cs[r][kk];
        float4 w = *(const float4*)&Ws[c][kk];
        acc = dot4acc(a, w, acc);
    }
    out[((size_t)(r0 + r) << 4) + c] = acc;
}

// ---------------- launcher ----------------
extern "C" void kernel_launch(void* const* d_in, const int* in_sizes, int n_in,
                              void* d_out, int out_size)
{
    const float* query = (const float*)d_in[0];
    const float* key   = (const float*)d_in[1];
    const float* value = (const float*)d_in[2];
    const float* Wq    = (const float*)d_in[3];
    const float* bq    = (const float*)d_in[4];
    const float* Wk    = (const float*)d_in[5];
    const float* bk    = (const float*)d_in[6];
    const float* Wv    = (const float*)d_in[7];
    const float* bv    = (const float*)d_in[8];
    const float* Wo    = (const float*)d_in[9];
    const float* bo    = (const float*)d_in[10];
    float* out = (float*)d_out;

    const float LOG2E = 1.4426950408889634f;
    const float alpha_q = 0.25f * LOG2E;

    dim3 gqk(MROWS / 32, 2);
    projqk_kernel<<<gqk, 128>>>(query, key, Wq, Wk, bq, bk, alpha_q);
    projv_kernel<<<(MROWS * 128) / 256, 256>>>(value, Wv, bv);
    attn_kernel<<<BHN * (NN / 128), 128>>>();
    outproj_kernel<<<MROWS / 16, 256>>>(Wo, bo, out);
}

// round 4
// speedup vs baseline: 1.3394x; 1.0013x over previous
#include <cuda_runtime.h>

// ---------------- problem constants ----------------
#define BB   4
#define HH   8
#define NN   2048
#define BHN  (BB*HH)          // 32
#define DHD  16               // head dim == v head dim
#define MROWS (BB*NN)         // 8192

typedef unsigned long long u64;

// ---------------- scratch (static device, no allocs) ----------------
__device__ float g_qs[BHN * NN * DHD];      // [bh][n][16], log2e*scaling folded in
__device__ float g_ks[BHN * NN * DHD];      // [bh][n][16]
__device__ float g_vs[BHN * NN * DHD];      // [bh][n][16]
__device__ float g_ctx[MROWS * 128];        // [b*N+n][h*16+e]

// ---------------- helpers ----------------
__device__ __forceinline__ float ex2f_fast(float x) {
    float y;
    asm("ex2.approx.ftz.f32 %0, %1;" : "=f"(y) : "f"(x));
    return y;
}
// packed fp32x2 ops (exact fp32 per lane, halves FFMA instruction count)
__device__ __forceinline__ u64 fmul2(u64 a, u64 b) {
    u64 d; asm("mul.rn.f32x2 %0, %1, %2;" : "=l"(d) : "l"(a), "l"(b)); return d;
}
__device__ __forceinline__ u64 ffma2(u64 a, u64 b, u64 c) {
    u64 d; asm("fma.rn.f32x2 %0, %1, %2, %3;" : "=l"(d) : "l"(a), "l"(b), "l"(c)); return d;
}
__device__ __forceinline__ u64 pack2(float lo, float hi) {
    u64 d; asm("mov.b64 %0, {%1, %2};" : "=l"(d) : "f"(lo), "f"(hi)); return d;
}
__device__ __forceinline__ float red2(u64 a) {
    float lo, hi; asm("mov.b64 {%0, %1}, %2;" : "=f"(lo), "=f"(hi) : "l"(a));
    return lo + hi;
}
__device__ __forceinline__ float dot4acc(float4 a, float4 b, float t) {
    t = fmaf(a.x, b.x, t); t = fmaf(a.y, b.y, t);
    t = fmaf(a.z, b.z, t); t = fmaf(a.w, b.w, t);
    return t;
}

// ---------------- Q/K projection ----------------
__global__ void __launch_bounds__(128) projqk_kernel(
    const float* __restrict__ Aq, const float* __restrict__ Ak,
    const float* __restrict__ Wq, const float* __restrict__ Wk,
    const float* __restrict__ bq, const float* __restrict__ bk,
    float alpha_q)
{
    const int TM = 32;
    __shared__ float As[TM][128];
    __shared__ float Ws[32][129];

    const bool is_k = (blockIdx.y != 0);
    const float* A    = is_k ? Ak : Aq;
    const float* W    = is_k ? Wk : Wq;
    const float* bias = is_k ? bk : bq;
    float*       outp = is_k ? g_ks : g_qs;
    const float alpha = is_k ? 1.0f : alpha_q;

    const int r0 = blockIdx.x * TM;
    const int c  = threadIdx.x;

    {
        const float4* Ag = (const float4*)(A + (size_t)r0 * 128);
        float4* Asv = (float4*)&As[0][0];
        #pragma unroll
        for (int i = 0; i < 8; i++) Asv[c + 128 * i] = Ag[c + 128 * i];
    }

    float acc[TM];
    #pragma unroll
    for (int r = 0; r < TM; r++) acc[r] = 0.f;

    for (int k0 = 0; k0 < 128; k0 += 32) {
        __syncthreads();
        const float4* wg = (const float4*)(W + c * 128 + k0);
        #pragma unroll
        for (int i = 0; i < 8; i++) {
            float4 w4 = wg[i];
            Ws[i * 4 + 0][c] = w4.x; Ws[i * 4 + 1][c] = w4.y;
            Ws[i * 4 + 2][c] = w4.z; Ws[i * 4 + 3][c] = w4.w;
        }
        __syncthreads();
        #pragma unroll
        for (int kk = 0; kk < 32; kk += 4) {
            const float w0 = Ws[kk + 0][c], w1 = Ws[kk + 1][c];
            const float w2 = Ws[kk + 2][c], w3 = Ws[kk + 3][c];
            #pragma unroll
            for (int r = 0; r < TM; r++) {
                float4 a4 = *(const float4*)&As[r][k0 + kk];
                float t = acc[r];
                t = fmaf(a4.x, w0, t); t = fmaf(a4.y, w1, t);
                t = fmaf(a4.z, w2, t); t = fmaf(a4.w, w3, t);
                acc[r] = t;
            }
        }
    }

    const float bc = bias[c];
    const int h = c >> 4, d = c & 15;
    #pragma unroll
    for (int r = 0; r < TM; r++) {
        const int row = r0 + r;
        const int b = row >> 11, n = row & 2047;
        outp[(((size_t)(b * HH + h) * NN + n) << 4) + d] = (acc[r] + bc) * alpha;
    }
}

// ---------------- V projection ----------------
__global__ void __launch_bounds__(256) projv_kernel(
    const float* __restrict__ value, const float* __restrict__ Wv,
    const float* __restrict__ bv)
{
    const int o = blockIdx.x * 256 + threadIdx.x;
    const int r = o >> 7, c = o & 127;
    const float4* a = (const float4*)(value + ((size_t)r << 4));
    const float4* w = (const float4*)(Wv + ((size_t)c << 4));
    float4 a0 = a[0], a1 = a[1], a2 = a[2], a3 = a[3];
    float4 w0 = w[0], w1 = w[1], w2 = w[2], w3 = w[3];
    float t = bv[c];
    t = dot4acc(a0, w0, t); t = dot4acc(a1, w1, t);
    t = dot4acc(a2, w2, t); t = dot4acc(a3, w3, t);
    const int b = r >> 11, n = r & 2047, h = c >> 4, d = c & 15;
    g_vs[(((size_t)(b * HH + h) * NN + n) << 4) + d] = t;
}

// ---------------- fused flash attention ----------------
// Round-1 launch shape (512 CTAs x 128 thr, 1 q-row/thread, 3.46 warps/SMSP)
// + f32x2 packed FFMA + LDS.128 staging (ulonglong2 halves feed FFMA2 directly).
__global__ void __launch_bounds__(128) attn_kernel()
{
    const int TK = 128;
    const int bh  = blockIdx.x >> 4;
    const int rt  = blockIdx.x & 15;
    const int tid = threadIdx.x;
    const int row = rt * 128 + tid;

    // q row as 8 packed f32x2
    const u64* qp = (const u64*)(g_qs + (((size_t)bh * NN + row) << 4));
    u64 q[8];
    #pragma unroll
    for (int i = 0; i < 8; i++) q[i] = qp[i];

    __shared__ __align__(16) ulonglong2 Ks[TK * 4];   // 8KB: 128 rows x 16 floats
    __shared__ __align__(16) ulonglong2 Vs[TK * 4];   // 8KB

    float m = -1e30f, l = 0.f;
    u64 o[8];
    const u64 zz = pack2(0.f, 0.f);
    #pragma unroll
    for (int i = 0; i < 8; i++) o[i] = zz;

    const ulonglong2* Kg = (const ulonglong2*)(g_ks + ((size_t)bh * NN << 4));
    const ulonglong2* Vg = (const ulonglong2*)(g_vs + ((size_t)bh * NN << 4));

    for (int t0 = 0; t0 < NN; t0 += TK) {
        __syncthreads();
        #pragma unroll
        for (int i = 0; i < 4; i++) {
            Ks[tid + 128 * i] = Kg[t0 * 4 + tid + 128 * i];
            Vs[tid + 128 * i] = Vg[t0 * 4 + tid + 128 * i];
        }
        __syncthreads();

        #pragma unroll 1
        for (int jc = 0; jc < TK; jc += 16) {
            float s[16];
            float cm = -1e30f;
            // scores: 16 keys, 8 FFMA2 each (4x LDS.128 per key, broadcast)
            #pragma unroll
            for (int jj = 0; jj < 16; jj++) {
                const ulonglong2* kr = &Ks[(jc + jj) * 4];
                ulonglong2 a0 = kr[0], a1 = kr[1], a2 = kr[2], a3 = kr[3];
                u64 acc = fmul2(q[0], a0.x);
                acc = ffma2(q[1], a0.y, acc);
                acc = ffma2(q[2], a1.x, acc);
                acc = ffma2(q[3], a1.y, acc);
                acc = ffma2(q[4], a2.x, acc);
                acc = ffma2(q[5], a2.y, acc);
                acc = ffma2(q[6], a3.x, acc);
                acc = ffma2(q[7], a3.y, acc);
                s[jj] = red2(acc);
                cm = fmaxf(cm, s[jj]);
            }
            // running-max correction (log2 domain)
            {
                const float mn = fmaxf(m, cm);
                const float c = ex2f_fast(m - mn);
                m = mn; l *= c;
                const u64 c2 = pack2(c, c);
                #pragma unroll
                for (int i = 0; i < 8; i++) o[i] = fmul2(o[i], c2);
            }
            // exp + PV accumulate (8 FFMA2 per key)
            #pragma unroll
            for (int jj = 0; jj < 16; jj++) {
                const ulonglong2* vr = &Vs[(jc + jj) * 4];
                const float p = ex2f_fast(s[jj] - m);
                l += p;
                const u64 pp = pack2(p, p);
                ulonglong2 v0 = vr[0], v1 = vr[1], v2 = vr[2], v3 = vr[3];
                o[0] = ffma2(pp, v0.x, o[0]);
                o[1] = ffma2(pp, v0.y, o[1]);
                o[2] = ffma2(pp, v1.x, o[2]);
                o[3] = ffma2(pp, v1.y, o[3]);
                o[4] = ffma2(pp, v2.x, o[4]);
                o[5] = ffma2(pp, v2.y, o[5]);
                o[6] = ffma2(pp, v3.x, o[6]);
                o[7] = ffma2(pp, v3.y, o[7]);
            }
        }
    }

    const float inv = 1.0f / l;
    const u64 i2 = pack2(inv, inv);
    #pragma unroll
    for (int i = 0; i < 8; i++) o[i] = fmul2(o[i], i2);

    const int b = bh >> 3, h = bh & 7;
    u64* op = (u64*)g_ctx + (((size_t)(b * NN + row)) << 6) + h * 8;
    #pragma unroll
    for (int i = 0; i < 8; i++) op[i] = o[i];
}

// ---------------- output projection: ctx[8192,128] @ Wo[16,128]^T + bo ----------------
__global__ void __launch_bounds__(256) outproj_kernel(
    const float* __restrict__ Wo, const float* __restrict__ bo,
    float* __restrict__ out)
{
    __shared__ float Cs[16][128];
    __shared__ float Ws[16][132];
    const int r0 = blockIdx.x * 16;

    const float4* cg = (const float4*)(g_ctx + ((size_t)r0 << 7));
    float4* csv = (float4*)&Cs[0][0];
    csv[threadIdx.x]       = cg[threadIdx.x];
    csv[threadIdx.x + 256] = cg[threadIdx.x + 256];
    for (int i = threadIdx.x; i < 2048; i += 256) Ws[i >> 7][i & 127] = Wo[i];
    __syncthreads();

    const int r = threadIdx.x >> 4, c = threadIdx.x & 15;
    float acc = bo[c];
    #pragma unroll
    for (int kk = 0; kk < 128; kk += 4) {
        float4 a = *(const float4*)&Cs[r][kk];
        float4 w = *(const float4*)&Ws[c][kk];
        acc = dot4acc(a, w, acc);
    }
    out[((size_t)(r0 + r) << 4) + c] = acc;
}

// ---------------- launcher ----------------
extern "C" void kernel_launch(void* const* d_in, const int* in_sizes, int n_in,
                              void* d_out, int out_size)
{
    const float* query = (const float*)d_in[0];
    const float* key   = (const float*)d_in[1];
    const float* value = (const float*)d_in[2];
    const float* Wq    = (const float*)d_in[3];
    const float* bq    = (const float*)d_in[4];
    const float* Wk    = (const float*)d_in[5];
    const float* bk    = (const float*)d_in[6];
    const float* Wv    = (const float*)d_in[7];
    const float* bv    = (const float*)d_in[8];
    const float* Wo    = (const float*)d_in[9];
    const float* bo    = (const float*)d_in[10];
    float* out = (float*)d_out;

    const float LOG2E = 1.4426950408889634f;
    const float alpha_q = 0.25f * LOG2E;

    dim3 gqk(MROWS / 32, 2);
    projqk_kernel<<<gqk, 128>>>(query, key, Wq, Wk, bq, bk, alpha_q);
    projv_kernel<<<(MROWS * 128) / 256, 256>>>(value, Wv, bv);
    attn_kernel<<<BHN * (NN / 128), 128>>>();
    outproj_kernel<<<MROWS / 16, 256>>>(Wo, bo, out);
}

// round 6
// speedup vs baseline: 3.2091x; 2.3959x over previous
#include <cuda_runtime.h>
#include <cuda_fp16.h>
#include <cstdint>

#define BB 4
#define HH 8
#define NN 2048
#define BHN (BB*HH)
#define MROWS (BB*NN)

// ---------------- scratch (static device, no allocs) ----------------
__device__ __half g_q16[BHN * NN * 32];   // [bh][n][qhi16|qlo16], 0.25*log2e folded
__device__ __half g_k16[BHN * NN * 32];   // [bh][n][khi16|klo16]
__device__ __half g_vh16[BHN * 16 * NN];  // [bh][e][n]  V^T hi
__device__ __half g_vl16[BHN * 16 * NN];  // [bh][e][n]  V^T lo
__device__ float  g_ctx[MROWS * 128];     // [b*N+n][h*16+e]

// ---------------- helpers ----------------
__device__ __forceinline__ float ex2f_fast(float x) {
    float y; asm("ex2.approx.ftz.f32 %0, %1;" : "=f"(y) : "f"(x)); return y;
}
__device__ __forceinline__ float dot4acc(float4 a, float4 b, float t) {
    t = fmaf(a.x, b.x, t); t = fmaf(a.y, b.y, t);
    t = fmaf(a.z, b.z, t); t = fmaf(a.w, b.w, t);
    return t;
}
__device__ __forceinline__ float qmax(float v) {
    v = fmaxf(v, __shfl_xor_sync(0xFFFFFFFFu, v, 1));
    v = fmaxf(v, __shfl_xor_sync(0xFFFFFFFFu, v, 2));
    return v;
}
__device__ __forceinline__ float qsum(float v) {
    v += __shfl_xor_sync(0xFFFFFFFFu, v, 1);
    v += __shfl_xor_sync(0xFFFFFFFFu, v, 2);
    return v;
}
// warp-level fp16 MMA, fp32 accumulate (HMMA fallback on sm_103a)
__device__ __forceinline__ void mma_f16(float* d, const uint32_t* a,
                                        uint32_t b0, uint32_t b1) {
    asm volatile(
        "mma.sync.aligned.m16n8k16.row.col.f32.f16.f16.f32 "
        "{%0,%1,%2,%3}, {%4,%5,%6,%7}, {%8,%9}, {%0,%1,%2,%3};"
        : "+f"(d[0]), "+f"(d[1]), "+f"(d[2]), "+f"(d[3])
        : "r"(a[0]), "r"(a[1]), "r"(a[2]), "r"(a[3]), "r"(b0), "r"(b1));
}
__device__ __forceinline__ uint32_t h2u(__half2 h) {
    return *reinterpret_cast<uint32_t*>(&h);
}

// ---------------- Q/K projection + fp16 hi/lo split ----------------
__global__ void __launch_bounds__(128) projqk_kernel(
    const float* __restrict__ Aq, const float* __restrict__ Ak,
    const float* __restrict__ Wq, const float* __restrict__ Wk,
    const float* __restrict__ bq, const float* __restrict__ bk, float alpha_q)
{
    const int TM = 32;
    __shared__ float As[TM][128];
    __shared__ float Ws[32][129];
    const bool is_k = (blockIdx.y != 0);
    const float* A    = is_k ? Ak : Aq;
    const float* W    = is_k ? Wk : Wq;
    const float* bias = is_k ? bk : bq;
    __half*      outp = is_k ? g_k16 : g_q16;
    const float alpha = is_k ? 1.0f : alpha_q;
    const int r0 = blockIdx.x * TM;
    const int c  = threadIdx.x;
    {
        const float4* Ag = (const float4*)(A + (size_t)r0 * 128);
        float4* Asv = (float4*)&As[0][0];
        #pragma unroll
        for (int i = 0; i < 8; i++) Asv[c + 128 * i] = Ag[c + 128 * i];
    }
    float acc[TM];
    #pragma unroll
    for (int r = 0; r < TM; r++) acc[r] = 0.f;
    for (int k0 = 0; k0 < 128; k0 += 32) {
        __syncthreads();
        const float4* wg = (const float4*)(W + c * 128 + k0);
        #pragma unroll
        for (int i = 0; i < 8; i++) {
            float4 w4 = wg[i];
            Ws[i*4+0][c] = w4.x; Ws[i*4+1][c] = w4.y;
            Ws[i*4+2][c] = w4.z; Ws[i*4+3][c] = w4.w;
        }
        __syncthreads();
        #pragma unroll
        for (int kk = 0; kk < 32; kk += 4) {
            const float w0 = Ws[kk+0][c], w1 = Ws[kk+1][c];
            const float w2 = Ws[kk+2][c], w3 = Ws[kk+3][c];
            #pragma unroll
            for (int r = 0; r < TM; r++) {
                float4 a4 = *(const float4*)&As[r][k0 + kk];
                float t = acc[r];
                t = fmaf(a4.x, w0, t); t = fmaf(a4.y, w1, t);
                t = fmaf(a4.z, w2, t); t = fmaf(a4.w, w3, t);
                acc[r] = t;
            }
        }
    }
    const float bc = bias[c];
    const int h = c >> 4, d = c & 15;
    #pragma unroll
    for (int r = 0; r < TM; r++) {
        const int row = r0 + r;
        const int b = row >> 11, n = row & 2047;
        const float x = (acc[r] + bc) * alpha;
        const __half hi = __float2half_rn(x);
        const size_t base = ((size_t)((b * HH + h) * NN + n)) * 32;
        outp[base + d]      = hi;
        outp[base + 16 + d] = __float2half_rn(x - __half2float(hi));
    }
}

// ---------------- V projection + transpose + fp16 hi/lo split ----------------
__global__ void __launch_bounds__(128) projvt_kernel(
    const float* __restrict__ value, const float* __restrict__ Wv,
    const float* __restrict__ bv)
{
    __shared__ float Wsm[16][17];
    __shared__ float bsm[16];
    __shared__ __half thi[16][128];
    __shared__ __half tlo[16][128];
    const int bh = blockIdx.x >> 4, nt = blockIdx.x & 15;
    const int b = bh >> 3, h = bh & 7;
    const int t = threadIdx.x;
    if (t < 16) bsm[t] = bv[h * 16 + t];
    for (int i = t; i < 256; i += 128)
        Wsm[i >> 4][i & 15] = Wv[(h * 16 + (i >> 4)) * 16 + (i & 15)];
    __syncthreads();
    const int n = nt * 128 + t;
    const float4* a = (const float4*)(value + ((size_t)(b * NN + n) << 4));
    const float4 a0 = a[0], a1 = a[1], a2 = a[2], a3 = a[3];
    const float av[16] = {a0.x,a0.y,a0.z,a0.w, a1.x,a1.y,a1.z,a1.w,
                          a2.x,a2.y,a2.z,a2.w, a3.x,a3.y,a3.z,a3.w};
    #pragma unroll
    for (int e = 0; e < 16; e++) {
        float acc = bsm[e];
        #pragma unroll
        for (int k = 0; k < 16; k++) acc = fmaf(av[k], Wsm[e][k], acc);
        const __half hi = __float2half_rn(acc);
        thi[e][t] = hi;
        tlo[e][t] = __float2half_rn(acc - __half2float(hi));
    }
    __syncthreads();
    for (int i = t; i < 2048; i += 128) {
        const int e = i >> 7, j = i & 127;
        const size_t o = ((size_t)bh * 16 + e) * NN + nt * 128 + j;
        g_vh16[o] = thi[e][j];
        g_vl16[o] = tlo[e][j];
    }
}

// ---------------- fp16 mma.sync flash attention ----------------
// 512 CTAs = 32 bh x 16 q-tiles of 128 rows; 4 warps; warp owns 32 q-rows
// (2 m16 blocks). S fragment lives in registers; P reuses S storage as
// packed fp16 hi/lo pairs (D layout == A layout for m16n8k16).
__global__ void __launch_bounds__(128) attn_mma_kernel()
{
    __shared__ __align__(16) __half Ksm[128 * 40];   // [key][hi16|lo16|pad8], 80B stride
    __shared__ __align__(16) __half Vh[16 * 136];    // [e][key], 272B stride
    __shared__ __align__(16) __half Vl[16 * 136];

    const int tid = threadIdx.x, lane = tid & 31, wid = tid >> 5;
    const int bh = blockIdx.x >> 4, qt = blockIdx.x & 15;
    const int qrow0 = qt * 128 + wid * 32;
    const int lq = lane >> 2;   // 0..7
    const int lc = lane & 3;    // 0..3

    // Q fragments hi/lo (one-time gmem load)
    uint32_t qh[2][4], ql[2][4];
    {
        const __half* qb = g_q16 + ((size_t)(bh * NN + qrow0)) * 32;
        #pragma unroll
        for (int m = 0; m < 2; m++) {
            const __half* p0 = qb + (m * 16 + lq) * 32 + lc * 2;
            qh[m][0] = *(const uint32_t*)(p0);
            qh[m][1] = *(const uint32_t*)(p0 + 256);
            qh[m][2] = *(const uint32_t*)(p0 + 8);
            qh[m][3] = *(const uint32_t*)(p0 + 264);
            ql[m][0] = *(const uint32_t*)(p0 + 16);
            ql[m][1] = *(const uint32_t*)(p0 + 272);
            ql[m][2] = *(const uint32_t*)(p0 + 24);
            ql[m][3] = *(const uint32_t*)(p0 + 280);
        }
    }

    float mr[4], lrow[4];
    float o[2][2][4];
    #pragma unroll
    for (int r = 0; r < 4; r++) { mr[r] = -1e30f; lrow[r] = 0.f; }
    #pragma unroll
    for (int m = 0; m < 2; m++)
        #pragma unroll
        for (int nb = 0; nb < 2; nb++)
            #pragma unroll
            for (int i = 0; i < 4; i++) o[m][nb][i] = 0.f;

    const uint4* kg = (const uint4*)(g_k16 + ((size_t)bh * NN) * 32);
    const __half* vhg = g_vh16 + (size_t)bh * 16 * NN;
    const __half* vlg = g_vl16 + (size_t)bh * 16 * NN;

    for (int t0 = 0; t0 < NN; t0 += 128) {
        __syncthreads();
        // stage K (coalesced 16B, conflict-light)
        #pragma unroll
        for (int g = 0; g < 4; g++) {
            const int j = tid + 128 * g;
            const int key = j >> 2, seg = j & 3;
            *(uint4*)(Ksm + key * 40 + seg * 8) = kg[(size_t)t0 * 4 + j];
        }
        // stage V^T hi/lo
        #pragma unroll
        for (int g = 0; g < 2; g++) {
            const int j = tid + 128 * g;
            const int e = j >> 4, seg = j & 15;
            *(uint4*)(Vh + e * 136 + seg * 8) = *(const uint4*)(vhg + (size_t)e * NN + t0 + seg * 8);
            *(uint4*)(Vl + e * 136 + seg * 8) = *(const uint4*)(vlg + (size_t)e * NN + t0 + seg * 8);
        }
        __syncthreads();

        // ---- QK: S = qhi*khi + qlo*khi + qhi*klo ----
        float S[2][16][4];
        #pragma unroll
        for (int m = 0; m < 2; m++)
            #pragma unroll
            for (int n = 0; n < 16; n++)
                #pragma unroll
                for (int i = 0; i < 4; i++) S[m][n][i] = 0.f;

        #pragma unroll
        for (int n = 0; n < 16; n++) {
            const __half* kb = Ksm + (n * 8 + lq) * 40 + lc * 2;
            const uint32_t bh0 = *(const uint32_t*)kb;
            const uint32_t bh1 = *(const uint32_t*)(kb + 8);
            const uint32_t bl0 = *(const uint32_t*)(kb + 16);
            const uint32_t bl1 = *(const uint32_t*)(kb + 24);
            #pragma unroll
            for (int m = 0; m < 2; m++) {
                mma_f16(S[m][n], qh[m], bh0, bh1);
                mma_f16(S[m][n], ql[m], bh0, bh1);
                mma_f16(S[m][n], qh[m], bl0, bl1);
            }
        }

        // ---- softmax (rows: l/4 + {0,8,16,24}) ----
        float cm[4] = {-1e30f, -1e30f, -1e30f, -1e30f};
        #pragma unroll
        for (int m = 0; m < 2; m++)
            #pragma unroll
            for (int n = 0; n < 16; n++) {
                cm[2*m]   = fmaxf(cm[2*m],   fmaxf(S[m][n][0], S[m][n][1]));
                cm[2*m+1] = fmaxf(cm[2*m+1], fmaxf(S[m][n][2], S[m][n][3]));
            }
        #pragma unroll
        for (int r = 0; r < 4; r++) {
            const float mn = fmaxf(mr[r], qmax(cm[r]));
            const float corr = ex2f_fast(mr[r] - mn);
            mr[r] = mn; lrow[r] *= corr;
            const int m = r >> 1, h2 = (r & 1) * 2;
            #pragma unroll
            for (int nb = 0; nb < 2; nb++) {
                o[m][nb][h2]   *= corr;
                o[m][nb][h2+1] *= corr;
            }
        }
        float rs[4] = {0.f, 0.f, 0.f, 0.f};
        #pragma unroll
        for (int m = 0; m < 2; m++)
            #pragma unroll
            for (int n = 0; n < 16; n++) {
                const float p0 = ex2f_fast(S[m][n][0] - mr[2*m]);
                const float p1 = ex2f_fast(S[m][n][1] - mr[2*m]);
                const float p2 = ex2f_fast(S[m][n][2] - mr[2*m+1]);
                const float p3 = ex2f_fast(S[m][n][3] - mr[2*m+1]);
                rs[2*m]   += p0 + p1;
                rs[2*m+1] += p2 + p3;
                const __half2 hA = __float22half2_rn(make_float2(p0, p1));
                const float2  bA = __half22float2(hA);
                const __half2 lA = __float22half2_rn(make_float2(p0 - bA.x, p1 - bA.y));
                const __half2 hB = __float22half2_rn(make_float2(p2, p3));
                const float2  bB = __half22float2(hB);
                const __half2 lB = __float22half2_rn(make_float2(p2 - bB.x, p3 - bB.y));
                S[m][n][0] = __uint_as_float(h2u(hA));
                S[m][n][1] = __uint_as_float(h2u(lA));
                S[m][n][2] = __uint_as_float(h2u(hB));
                S[m][n][3] = __uint_as_float(h2u(lB));
            }
        #pragma unroll
        for (int r = 0; r < 4; r++) lrow[r] += qsum(rs[r]);

        // ---- PV: o += Phi*Vhi + Plo*Vhi + Phi*Vlo ----
        #pragma unroll
        for (int kb = 0; kb < 8; kb++) {
            #pragma unroll
            for (int nb = 0; nb < 2; nb++) {
                const __half* vb  = Vh + (nb * 8 + lq) * 136 + kb * 16 + lc * 2;
                const __half* vbl = Vl + (nb * 8 + lq) * 136 + kb * 16 + lc * 2;
                const uint32_t b0 = *(const uint32_t*)vb;
                const uint32_t b1 = *(const uint32_t*)(vb + 8);
                const uint32_t c0 = *(const uint32_t*)vbl;
                const uint32_t c1 = *(const uint32_t*)(vbl + 8);
                #pragma unroll
                for (int m = 0; m < 2; m++) {
                    const uint32_t ah[4] = {
                        __float_as_uint(S[m][2*kb][0]),   __float_as_uint(S[m][2*kb][2]),
                        __float_as_uint(S[m][2*kb+1][0]), __float_as_uint(S[m][2*kb+1][2])
                    };
                    const uint32_t al[4] = {
                        __float_as_uint(S[m][2*kb][1]),   __float_as_uint(S[m][2*kb][3]),
                        __float_as_uint(S[m][2*kb+1][1]), __float_as_uint(S[m][2*kb+1][3])
                    };
                    mma_f16(o[m][nb], ah, b0, b1);
                    mma_f16(o[m][nb], al, b0, b1);
                    mma_f16(o[m][nb], ah, c0, c1);
                }
            }
        }
    }

    // ---- epilogue ----
    float inv[4];
    #pragma unroll
    for (int r = 0; r < 4; r++) inv[r] = 1.0f / lrow[r];
    const int b = bh >> 3, hh = bh & 7;
    #pragma unroll
    for (int m = 0; m < 2; m++) {
        const int rA = qrow0 + m * 16 + lq;
        #pragma unroll
        for (int nb = 0; nb < 2; nb++) {
            const int e0 = nb * 8 + lc * 2;
            float* pA = g_ctx + ((size_t)(b * NN + rA)) * 128 + hh * 16 + e0;
            float* pB = pA + 8 * 128;
            *(float2*)pA = make_float2(o[m][nb][0] * inv[2*m],   o[m][nb][1] * inv[2*m]);
            *(float2*)pB = make_float2(o[m][nb][2] * inv[2*m+1], o[m][nb][3] * inv[2*m+1]);
        }
    }
}

// ---------------- output projection ----------------
__global__ void __launch_bounds__(256) outproj_kernel(
    const float* __restrict__ Wo, const float* __restrict__ bo,
    float* __restrict__ out)
{
    __shared__ float Cs[16][128];
    __shared__ float Ws[16][132];
    const int r0 = blockIdx.x * 16;
    const float4* cg = (const float4*)(g_ctx + ((size_t)r0 << 7));
    float4* csv = (float4*)&Cs[0][0];
    csv[threadIdx.x]       = cg[threadIdx.x];
    csv[threadIdx.x + 256] = cg[threadIdx.x + 256];
    for (int i = threadIdx.x; i < 2048; i += 256) Ws[i >> 7][i & 127] = Wo[i];
    __syncthreads();
    const int r = threadIdx.x >> 4, c = threadIdx.x & 15;
    float acc = bo[c];
    #pragma unroll
    for (int kk = 0; kk < 128; kk += 4) {
        float4 a = *(const float4*)&Cs[r][kk];
        float4 w = *(const float4*)&Ws[c][kk];
        acc = dot4acc(a, w, acc);
    }
    out[((size_t)(r0 + r) << 4) + c] = acc;
}

// ---------------- launcher ----------------
extern "C" void kernel_launch(void* const* d_in, const int* in_sizes, int n_in,
                              void* d_out, int out_size)
{
    const float* query = (const float*)d_in[0];
    const float* key   = (const float*)d_in[1];
    const float* value = (const float*)d_in[2];
    const float* Wq    = (const float*)d_in[3];
    const float* bq    = (const float*)d_in[4];
    const float* Wk    = (const float*)d_in[5];
    const float* bk    = (const float*)d_in[6];
    const float* Wv    = (const float*)d_in[7];
    const float* bv    = (const float*)d_in[8];
    const float* Wo    = (const float*)d_in[9];
    const float* bo    = (const float*)d_in[10];
    float* out = (float*)d_out;

    const float alpha_q = 0.25f * 1.4426950408889634f;

    dim3 gqk(MROWS / 32, 2);
    projqk_kernel<<<gqk, 128>>>(query, key, Wq, Wk, bq, bk, alpha_q);
    projvt_kernel<<<BHN * 16, 128>>>(value, Wv, bv);
    attn_mma_kernel<<<BHN * 16, 128>>>();
    outproj_kernel<<<MROWS / 16, 256>>>(Wo, bo, out);
}

// round 7
// speedup vs baseline: 3.8514x; 1.2002x over previous
#include <cuda_runtime.h>
#include <cuda_fp16.h>
#include <cstdint>

#define BB 4
#define HH 8
#define NN 2048
#define BHN (BB*HH)
#define MROWS (BB*NN)

// ---------------- scratch (static device, no allocs) ----------------
__device__ __half g_q16[BHN * NN * 32];   // [bh][n][qhi16|qlo16], 0.25*log2e folded
__device__ __half g_k16[BHN * NN * 32];   // [bh][n][khi16|klo16]
__device__ __half g_vh16[BHN * 16 * NN];  // [bh][e][n]  V^T hi
__device__ __half g_vl16[BHN * 16 * NN];  // [bh][e][n]  V^T lo
__device__ float  g_ctx[MROWS * 128];     // [b*N+n][h*16+e]

// ---------------- helpers ----------------
__device__ __forceinline__ float ex2f_fast(float x) {
    float y; asm("ex2.approx.ftz.f32 %0, %1;" : "=f"(y) : "f"(x)); return y;
}
__device__ __forceinline__ float dot4acc(float4 a, float4 b, float t) {
    t = fmaf(a.x, b.x, t); t = fmaf(a.y, b.y, t);
    t = fmaf(a.z, b.z, t); t = fmaf(a.w, b.w, t);
    return t;
}
__device__ __forceinline__ float qmax(float v) {
    v = fmaxf(v, __shfl_xor_sync(0xFFFFFFFFu, v, 1));
    v = fmaxf(v, __shfl_xor_sync(0xFFFFFFFFu, v, 2));
    return v;
}
__device__ __forceinline__ float qsum(float v) {
    v += __shfl_xor_sync(0xFFFFFFFFu, v, 1);
    v += __shfl_xor_sync(0xFFFFFFFFu, v, 2);
    return v;
}
__device__ __forceinline__ void mma_f16(float* d, const uint32_t* a,
                                        uint32_t b0, uint32_t b1) {
    asm volatile(
        "mma.sync.aligned.m16n8k16.row.col.f32.f16.f16.f32 "
        "{%0,%1,%2,%3}, {%4,%5,%6,%7}, {%8,%9}, {%0,%1,%2,%3};"
        : "+f"(d[0]), "+f"(d[1]), "+f"(d[2]), "+f"(d[3])
        : "r"(a[0]), "r"(a[1]), "r"(a[2]), "r"(a[3]), "r"(b0), "r"(b1));
}
__device__ __forceinline__ uint32_t cvt_h2(float lo, float hi) {
    uint32_t r;
    asm("cvt.rn.f16x2.f32 %0, %1, %2;" : "=r"(r) : "f"(hi), "f"(lo));
    return r;
}

// ---------------- Q/K projection + fp16 hi/lo split ----------------
__global__ void __launch_bounds__(128) projqk_kernel(
    const float* __restrict__ Aq, const float* __restrict__ Ak,
    const float* __restrict__ Wq, const float* __restrict__ Wk,
    const float* __restrict__ bq, const float* __restrict__ bk, float alpha_q)
{
    const int TM = 32;
    __shared__ float As[TM][128];
    __shared__ float Ws[32][129];
    const bool is_k = (blockIdx.y != 0);
    const float* A    = is_k ? Ak : Aq;
    const float* W    = is_k ? Wk : Wq;
    const float* bias = is_k ? bk : bq;
    __half*      outp = is_k ? g_k16 : g_q16;
    const float alpha = is_k ? 1.0f : alpha_q;
    const int r0 = blockIdx.x * TM;
    const int c  = threadIdx.x;
    {
        const float4* Ag = (const float4*)(A + (size_t)r0 * 128);
        float4* Asv = (float4*)&As[0][0];
        #pragma unroll
        for (int i = 0; i < 8; i++) Asv[c + 128 * i] = Ag[c + 128 * i];
    }
    float acc[TM];
    #pragma unroll
    for (int r = 0; r < TM; r++) acc[r] = 0.f;
    for (int k0 = 0; k0 < 128; k0 += 32) {
        __syncthreads();
        const float4* wg = (const float4*)(W + c * 128 + k0);
        #pragma unroll
        for (int i = 0; i < 8; i++) {
            float4 w4 = wg[i];
            Ws[i*4+0][c] = w4.x; Ws[i*4+1][c] = w4.y;
            Ws[i*4+2][c] = w4.z; Ws[i*4+3][c] = w4.w;
        }
        __syncthreads();
        #pragma unroll
        for (int kk = 0; kk < 32; kk += 4) {
            const float w0 = Ws[kk+0][c], w1 = Ws[kk+1][c];
            const float w2 = Ws[kk+2][c], w3 = Ws[kk+3][c];
            #pragma unroll
            for (int r = 0; r < TM; r++) {
                float4 a4 = *(const float4*)&As[r][k0 + kk];
                float t = acc[r];
                t = fmaf(a4.x, w0, t); t = fmaf(a4.y, w1, t);
                t = fmaf(a4.z, w2, t); t = fmaf(a4.w, w3, t);
                acc[r] = t;
            }
        }
    }
    const float bc = bias[c];
    const int h = c >> 4, d = c & 15;
    #pragma unroll
    for (int r = 0; r < TM; r++) {
        const int row = r0 + r;
        const int b = row >> 11, n = row & 2047;
        const float x = (acc[r] + bc) * alpha;
        const __half hi = __float2half_rn(x);
        const size_t base = ((size_t)((b * HH + h) * NN + n)) * 32;
        outp[base + d]      = hi;
        outp[base + 16 + d] = __float2half_rn(x - __half2float(hi));
    }
}

// ---------------- V projection + transpose + fp16 hi/lo split ----------------
__global__ void __launch_bounds__(128) projvt_kernel(
    const float* __restrict__ value, const float* __restrict__ Wv,
    const float* __restrict__ bv)
{
    __shared__ float Wsm[16][17];
    __shared__ float bsm[16];
    __shared__ __half thi[16][128];
    __shared__ __half tlo[16][128];
    const int bh = blockIdx.x >> 4, nt = blockIdx.x & 15;
    const int b = bh >> 3, h = bh & 7;
    const int t = threadIdx.x;
    if (t < 16) bsm[t] = bv[h * 16 + t];
    for (int i = t; i < 256; i += 128)
        Wsm[i >> 4][i & 15] = Wv[(h * 16 + (i >> 4)) * 16 + (i & 15)];
    __syncthreads();
    const int n = nt * 128 + t;
    const float4* a = (const float4*)(value + ((size_t)(b * NN + n) << 4));
    const float4 a0 = a[0], a1 = a[1], a2 = a[2], a3 = a[3];
    const float av[16] = {a0.x,a0.y,a0.z,a0.w, a1.x,a1.y,a1.z,a1.w,
                          a2.x,a2.y,a2.z,a2.w, a3.x,a3.y,a3.z,a3.w};
    #pragma unroll
    for (int e = 0; e < 16; e++) {
        float acc = bsm[e];
        #pragma unroll
        for (int k = 0; k < 16; k++) acc = fmaf(av[k], Wsm[e][k], acc);
        const __half hi = __float2half_rn(acc);
        thi[e][t] = hi;
        tlo[e][t] = __float2half_rn(acc - __half2float(hi));
    }
    __syncthreads();
    for (int i = t; i < 2048; i += 128) {
        const int e = i >> 7, j = i & 127;
        const size_t o = ((size_t)bh * 16 + e) * NN + nt * 128 + j;
        g_vh16[o] = thi[e][j];
        g_vl16[o] = tlo[e][j];
    }
}

// ---------------- fp16 mma.sync flash attention ----------------
// QK: 3 compensated MMAs (qhi*khi + qlo*khi + qhi*klo).
// PV: 2 MMAs (Phi*Vhi + Phi*Vlo) — P residual dropped (rel err ~1e-4).
__global__ void __launch_bounds__(128) attn_mma_kernel()
{
    __shared__ __align__(16) __half Ksm[128 * 40];   // [key][hi16|lo16|pad8], 80B stride
    __shared__ __align__(16) __half Vh[16 * 136];    // [e][key], 272B stride
    __shared__ __align__(16) __half Vl[16 * 136];

    const int tid = threadIdx.x, lane = tid & 31, wid = tid >> 5;
    const int bh = blockIdx.x >> 4, qt = blockIdx.x & 15;
    const int qrow0 = qt * 128 + wid * 32;
    const int lq = lane >> 2;   // 0..7
    const int lc = lane & 3;    // 0..3

    // Q fragments hi/lo (one-time gmem load)
    uint32_t qh[2][4], ql[2][4];
    {
        const __half* qb = g_q16 + ((size_t)(bh * NN + qrow0)) * 32;
        #pragma unroll
        for (int m = 0; m < 2; m++) {
            const __half* p0 = qb + (m * 16 + lq) * 32 + lc * 2;
            qh[m][0] = *(const uint32_t*)(p0);
            qh[m][1] = *(const uint32_t*)(p0 + 256);
            qh[m][2] = *(const uint32_t*)(p0 + 8);
            qh[m][3] = *(const uint32_t*)(p0 + 264);
            ql[m][0] = *(const uint32_t*)(p0 + 16);
            ql[m][1] = *(const uint32_t*)(p0 + 272);
            ql[m][2] = *(const uint32_t*)(p0 + 24);
            ql[m][3] = *(const uint32_t*)(p0 + 280);
        }
    }

    float mr[4], lrow[4];
    float o[2][2][4];
    #pragma unroll
    for (int r = 0; r < 4; r++) { mr[r] = -1e30f; lrow[r] = 0.f; }
    #pragma unroll
    for (int m = 0; m < 2; m++)
        #pragma unroll
        for (int nb = 0; nb < 2; nb++)
            #pragma unroll
            for (int i = 0; i < 4; i++) o[m][nb][i] = 0.f;

    const uint4* kg = (const uint4*)(g_k16 + ((size_t)bh * NN) * 32);
    const __half* vhg = g_vh16 + (size_t)bh * 16 * NN;
    const __half* vlg = g_vl16 + (size_t)bh * 16 * NN;

    for (int t0 = 0; t0 < NN; t0 += 128) {
        __syncthreads();
        #pragma unroll
        for (int g = 0; g < 4; g++) {
            const int j = tid + 128 * g;
            const int key = j >> 2, seg = j & 3;
            *(uint4*)(Ksm + key * 40 + seg * 8) = kg[(size_t)t0 * 4 + j];
        }
        #pragma unroll
        for (int g = 0; g < 2; g++) {
            const int j = tid + 128 * g;
            const int e = j >> 4, seg = j & 15;
            *(uint4*)(Vh + e * 136 + seg * 8) = *(const uint4*)(vhg + (size_t)e * NN + t0 + seg * 8);
            *(uint4*)(Vl + e * 136 + seg * 8) = *(const uint4*)(vlg + (size_t)e * NN + t0 + seg * 8);
        }
        __syncthreads();

        // ---- QK ----
        float S[2][16][4];
        #pragma unroll
        for (int m = 0; m < 2; m++)
            #pragma unroll
            for (int n = 0; n < 16; n++)
                #pragma unroll
                for (int i = 0; i < 4; i++) S[m][n][i] = 0.f;

        #pragma unroll
        for (int n = 0; n < 16; n++) {
            const __half* kb = Ksm + (n * 8 + lq) * 40 + lc * 2;
            const uint32_t bh0 = *(const uint32_t*)kb;
            const uint32_t bh1 = *(const uint32_t*)(kb + 8);
            const uint32_t bl0 = *(const uint32_t*)(kb + 16);
            const uint32_t bl1 = *(const uint32_t*)(kb + 24);
            #pragma unroll
            for (int m = 0; m < 2; m++) {
                mma_f16(S[m][n], qh[m], bh0, bh1);
                mma_f16(S[m][n], ql[m], bh0, bh1);
                mma_f16(S[m][n], qh[m], bl0, bl1);
            }
        }

        // ---- softmax (rows: lq + {0,8,16,24}) ----
        float cm[4] = {-1e30f, -1e30f, -1e30f, -1e30f};
        #pragma unroll
        for (int m = 0; m < 2; m++)
            #pragma unroll
            for (int n = 0; n < 16; n++) {
                cm[2*m]   = fmaxf(cm[2*m],   fmaxf(S[m][n][0], S[m][n][1]));
                cm[2*m+1] = fmaxf(cm[2*m+1], fmaxf(S[m][n][2], S[m][n][3]));
            }
        #pragma unroll
        for (int r = 0; r < 4; r++) {
            const float mn = fmaxf(mr[r], qmax(cm[r]));
            const float corr = ex2f_fast(mr[r] - mn);
            mr[r] = mn; lrow[r] *= corr;
            const int m = r >> 1, h2 = (r & 1) * 2;
            #pragma unroll
            for (int nb = 0; nb < 2; nb++) {
                o[m][nb][h2]   *= corr;
                o[m][nb][h2+1] *= corr;
            }
        }
        float rs[4] = {0.f, 0.f, 0.f, 0.f};
        #pragma unroll
        for (int m = 0; m < 2; m++)
            #pragma unroll
            for (int n = 0; n < 16; n++) {
                const float p0 = ex2f_fast(S[m][n][0] - mr[2*m]);
                const float p1 = ex2f_fast(S[m][n][1] - mr[2*m]);
                const float p2 = ex2f_fast(S[m][n][2] - mr[2*m+1]);
                const float p3 = ex2f_fast(S[m][n][3] - mr[2*m+1]);
                rs[2*m]   += p0 + p1;
                rs[2*m+1] += p2 + p3;
                S[m][n][0] = __uint_as_float(cvt_h2(p0, p1));  // keys (2lc, 2lc+1), row lq
                S[m][n][1] = __uint_as_float(cvt_h2(p2, p3));  // keys (2lc, 2lc+1), row lq+8
            }
        #pragma unroll
        for (int r = 0; r < 4; r++) lrow[r] += qsum(rs[r]);

        // ---- PV: o += Phi*Vhi + Phi*Vlo ----
        #pragma unroll
        for (int kb = 0; kb < 8; kb++) {
            #pragma unroll
            for (int nb = 0; nb < 2; nb++) {
                const __half* vb  = Vh + (nb * 8 + lq) * 136 + kb * 16 + lc * 2;
                const __half* vbl = Vl + (nb * 8 + lq) * 136 + kb * 16 + lc * 2;
                const uint32_t b0 = *(const uint32_t*)vb;
                const uint32_t b1 = *(const uint32_t*)(vb + 8);
                const uint32_t c0 = *(const uint32_t*)vbl;
                const uint32_t c1 = *(const uint32_t*)(vbl + 8);
                #pragma unroll
                for (int m = 0; m < 2; m++) {
                    const uint32_t ah[4] = {
                        __float_as_uint(S[m][2*kb][0]),   __float_as_uint(S[m][2*kb][1]),
                        __float_as_uint(S[m][2*kb+1][0]), __float_as_uint(S[m][2*kb+1][1])
                    };
                    mma_f16(o[m][nb], ah, b0, b1);
                    mma_f16(o[m][nb], ah, c0, c1);
                }
            }
        }
    }

    // ---- epilogue ----
    float inv[4];
    #pragma unroll
    for (int r = 0; r < 4; r++) inv[r] = 1.0f / lrow[r];
    const int b = bh >> 3, hh = bh & 7;
    #pragma unroll
    for (int m = 0; m < 2; m++) {
        const int rA = qrow0 + m * 16 + lq;
        #pragma unroll
        for (int nb = 0; nb < 2; nb++) {
            const int e0 = nb * 8 + lc * 2;
            float* pA = g_ctx + ((size_t)(b * NN + rA)) * 128 + hh * 16 + e0;
            float* pB = pA + 8 * 128;
            *(float2*)pA = make_float2(o[m][nb][0] * inv[2*m],   o[m][nb][1] * inv[2*m]);
            *(float2*)pB = make_float2(o[m][nb][2] * inv[2*m+1], o[m][nb][3] * inv[2*m+1]);
        }
    }
}

// ---------------- output projection ----------------
__global__ void __launch_bounds__(256) outproj_kernel(
    const float* __restrict__ Wo, const float* __restrict__ bo,
    float* __restrict__ out)
{
    __shared__ float Cs[16][128];
    __shared__ float Ws[16][132];
    const int r0 = blockIdx.x * 16;
    const float4* cg = (const float4*)(g_ctx + ((size_t)r0 << 7));
    float4* csv = (float4*)&Cs[0][0];
    csv[threadIdx.x]       = cg[threadIdx.x];
    csv[threadIdx.x + 256] = cg[threadIdx.x + 256];
    for (int i = threadIdx.x; i < 2048; i += 256) Ws[i >> 7][i & 127] = Wo[i];
    __syncthreads();
    const int r = threadIdx.x >> 4, c = threadIdx.x & 15;
    float acc = bo[c];
    #pragma unroll
    for (int kk = 0; kk < 128; kk += 4) {
        float4 a = *(const float4*)&Cs[r][kk];
        float4 w = *(const float4*)&Ws[c][kk];
        acc = dot4acc(a, w, acc);
    }
    out[((size_t)(r0 + r) << 4) + c] = acc;
}

// ---------------- launcher ----------------
extern "C" void kernel_launch(void* const* d_in, const int* in_sizes, int n_in,
                              void* d_out, int out_size)
{
    const float* query = (const float*)d_in[0];
    const float* key   = (const float*)d_in[1];
    const float* value = (const float*)d_in[2];
    const float* Wq    = (const float*)d_in[3];
    const float* bq    = (const float*)d_in[4];
    const float* Wk    = (const float*)d_in[5];
    const float* bk    = (const float*)d_in[6];
    const float* Wv    = (const float*)d_in[7];
    const float* bv    = (const float*)d_in[8];
    const float* Wo    = (const float*)d_in[9];
    const float* bo    = (const float*)d_in[10];
    float* out = (float*)d_out;

    const float alpha_q = 0.25f * 1.4426950408889634f;

    dim3 gqk(MROWS / 32, 2);
    projqk_kernel<<<gqk, 128>>>(query, key, Wq, Wk, bq, bk, alpha_q);
    projvt_kernel<<<BHN * 16, 128>>>(value, Wv, bv);
    attn_mma_kernel<<<BHN * 16, 128>>>();
    outproj_kernel<<<MROWS / 16, 256>>>(Wo, bo, out);
}

// round 8
// speedup vs baseline: 4.0174x; 1.0431x over previous
#include <cuda_runtime.h>
#include <cuda_fp16.h>
#include <cstdint>

#define BB 4
#define HH 8
#define NN 2048
#define BHN (BB*HH)
#define MROWS (BB*NN)

// ---------------- scratch (static device, no allocs) ----------------
__device__ __half g_q16[BHN * NN * 32];   // [bh][n][qhi16|qlo16], 0.25*log2e folded
__device__ __half g_k16[BHN * NN * 32];   // [bh][n][khi16|klo16]
__device__ __half g_vh16[BHN * 16 * NN];  // [bh][e][n]  V^T (fp16-rn)
__device__ float  g_ctx[MROWS * 128];     // [b*N+n][h*16+e]

// ---------------- helpers ----------------
__device__ __forceinline__ float ex2f_fast(float x) {
    float y; asm("ex2.approx.ftz.f32 %0, %1;" : "=f"(y) : "f"(x)); return y;
}
__device__ __forceinline__ float dot4acc(float4 a, float4 b, float t) {
    t = fmaf(a.x, b.x, t); t = fmaf(a.y, b.y, t);
    t = fmaf(a.z, b.z, t); t = fmaf(a.w, b.w, t);
    return t;
}
__device__ __forceinline__ float qmax(float v) {
    v = fmaxf(v, __shfl_xor_sync(0xFFFFFFFFu, v, 1));
    v = fmaxf(v, __shfl_xor_sync(0xFFFFFFFFu, v, 2));
    return v;
}
__device__ __forceinline__ float qsum(float v) {
    v += __shfl_xor_sync(0xFFFFFFFFu, v, 1);
    v += __shfl_xor_sync(0xFFFFFFFFu, v, 2);
    return v;
}
__device__ __forceinline__ void mma_f16(float* d, const uint32_t* a,
                                        uint32_t b0, uint32_t b1) {
    asm volatile(
        "mma.sync.aligned.m16n8k16.row.col.f32.f16.f16.f32 "
        "{%0,%1,%2,%3}, {%4,%5,%6,%7}, {%8,%9}, {%0,%1,%2,%3};"
        : "+f"(d[0]), "+f"(d[1]), "+f"(d[2]), "+f"(d[3])
        : "r"(a[0]), "r"(a[1]), "r"(a[2]), "r"(a[3]), "r"(b0), "r"(b1));
}
__device__ __forceinline__ uint32_t cvt_h2(float lo, float hi) {
    uint32_t r;
    asm("cvt.rn.f16x2.f32 %0, %1, %2;" : "=r"(r) : "f"(hi), "f"(lo));
    return r;
}

// ---------------- Q/K projection + fp16 hi/lo split ----------------
__global__ void __launch_bounds__(128) projqk_kernel(
    const float* __restrict__ Aq, const float* __restrict__ Ak,
    const float* __restrict__ Wq, const float* __restrict__ Wk,
    const float* __restrict__ bq, const float* __restrict__ bk, float alpha_q)
{
    const int TM = 32;
    __shared__ float As[TM][128];
    __shared__ float Ws[32][129];
    const bool is_k = (blockIdx.y != 0);
    const float* A    = is_k ? Ak : Aq;
    const float* W    = is_k ? Wk : Wq;
    const float* bias = is_k ? bk : bq;
    __half*      outp = is_k ? g_k16 : g_q16;
    const float alpha = is_k ? 1.0f : alpha_q;
    const int r0 = blockIdx.x * TM;
    const int c  = threadIdx.x;
    {
        const float4* Ag = (const float4*)(A + (size_t)r0 * 128);
        float4* Asv = (float4*)&As[0][0];
        #pragma unroll
        for (int i = 0; i < 8; i++) Asv[c + 128 * i] = Ag[c + 128 * i];
    }
    float acc[TM];
    #pragma unroll
    for (int r = 0; r < TM; r++) acc[r] = 0.f;
    for (int k0 = 0; k0 < 128; k0 += 32) {
        __syncthreads();
        const float4* wg = (const float4*)(W + c * 128 + k0);
        #pragma unroll
        for (int i = 0; i < 8; i++) {
            float4 w4 = wg[i];
            Ws[i*4+0][c] = w4.x; Ws[i*4+1][c] = w4.y;
            Ws[i*4+2][c] = w4.z; Ws[i*4+3][c] = w4.w;
        }
        __syncthreads();
        #pragma unroll
        for (int kk = 0; kk < 32; kk += 4) {
            const float w0 = Ws[kk+0][c], w1 = Ws[kk+1][c];
            const float w2 = Ws[kk+2][c], w3 = Ws[kk+3][c];
            #pragma unroll
            for (int r = 0; r < TM; r++) {
                float4 a4 = *(const float4*)&As[r][k0 + kk];
                float t = acc[r];
                t = fmaf(a4.x, w0, t); t = fmaf(a4.y, w1, t);
                t = fmaf(a4.z, w2, t); t = fmaf(a4.w, w3, t);
                acc[r] = t;
            }
        }
    }
    const float bc = bias[c];
    const int h = c >> 4, d = c & 15;
    #pragma unroll
    for (int r = 0; r < TM; r++) {
        const int row = r0 + r;
        const int b = row >> 11, n = row & 2047;
        const float x = (acc[r] + bc) * alpha;
        const __half hi = __float2half_rn(x);
        const size_t base = ((size_t)((b * HH + h) * NN + n)) * 32;
        outp[base + d]      = hi;
        outp[base + 16 + d] = __float2half_rn(x - __half2float(hi));
    }
}

// ---------------- V projection + transpose (fp16-rn) ----------------
__global__ void __launch_bounds__(128) projvt_kernel(
    const float* __restrict__ value, const float* __restrict__ Wv,
    const float* __restrict__ bv)
{
    __shared__ float Wsm[16][17];
    __shared__ float bsm[16];
    __shared__ __half thi[16][128];
    const int bh = blockIdx.x >> 4, nt = blockIdx.x & 15;
    const int b = bh >> 3, h = bh & 7;
    const int t = threadIdx.x;
    if (t < 16) bsm[t] = bv[h * 16 + t];
    for (int i = t; i < 256; i += 128)
        Wsm[i >> 4][i & 15] = Wv[(h * 16 + (i >> 4)) * 16 + (i & 15)];
    __syncthreads();
    const int n = nt * 128 + t;
    const float4* a = (const float4*)(value + ((size_t)(b * NN + n) << 4));
    const float4 a0 = a[0], a1 = a[1], a2 = a[2], a3 = a[3];
    const float av[16] = {a0.x,a0.y,a0.z,a0.w, a1.x,a1.y,a1.z,a1.w,
                          a2.x,a2.y,a2.z,a2.w, a3.x,a3.y,a3.z,a3.w};
    #pragma unroll
    for (int e = 0; e < 16; e++) {
        float acc = bsm[e];
        #pragma unroll
        for (int k = 0; k < 16; k++) acc = fmaf(av[k], Wsm[e][k], acc);
        thi[e][t] = __float2half_rn(acc);
    }
    __syncthreads();
    for (int i = t; i < 2048; i += 128) {
        const int e = i >> 7, j = i & 127;
        g_vh16[((size_t)bh * 16 + e) * NN + nt * 128 + j] = thi[e][j];
    }
}

// ---------------- fp16 mma.sync flash attention ----------------
// QK: 3 compensated MMAs (qhi*khi + qlo*khi + qhi*klo) — needed for score accuracy.
// PV: 1 MMA per fragment (Phi*V, V fp16-rn; rel err ~1.4e-4).
__global__ void __launch_bounds__(128) attn_mma_kernel()
{
    __shared__ __align__(16) __half Ksm[128 * 40];   // [key][hi16|lo16|pad8], 80B stride
    __shared__ __align__(16) __half Vh[16 * 136];    // [e][key], 272B stride

    const int tid = threadIdx.x, lane = tid & 31, wid = tid >> 5;
    const int bh = blockIdx.x >> 4, qt = blockIdx.x & 15;
    const int qrow0 = qt * 128 + wid * 32;
    const int lq = lane >> 2;   // 0..7
    const int lc = lane & 3;    // 0..3

    // Q fragments hi/lo (one-time gmem load)
    uint32_t qh[2][4], ql[2][4];
    {
        const __half* qb = g_q16 + ((size_t)(bh * NN + qrow0)) * 32;
        #pragma unroll
        for (int m = 0; m < 2; m++) {
            const __half* p0 = qb + (m * 16 + lq) * 32 + lc * 2;
            qh[m][0] = *(const uint32_t*)(p0);
            qh[m][1] = *(const uint32_t*)(p0 + 256);
            qh[m][2] = *(const uint32_t*)(p0 + 8);
            qh[m][3] = *(const uint32_t*)(p0 + 264);
            ql[m][0] = *(const uint32_t*)(p0 + 16);
            ql[m][1] = *(const uint32_t*)(p0 + 272);
            ql[m][2] = *(const uint32_t*)(p0 + 24);
            ql[m][3] = *(const uint32_t*)(p0 + 280);
        }
    }

    float mr[4], lrow[4];
    float o[2][2][4];
    #pragma unroll
    for (int r = 0; r < 4; r++) { mr[r] = -1e30f; lrow[r] = 0.f; }
    #pragma unroll
    for (int m = 0; m < 2; m++)
        #pragma unroll
        for (int nb = 0; nb < 2; nb++)
            #pragma unroll
            for (int i = 0; i < 4; i++) o[m][nb][i] = 0.f;

    const uint4* kg = (const uint4*)(g_k16 + ((size_t)bh * NN) * 32);
    const __half* vhg = g_vh16 + (size_t)bh * 16 * NN;

    for (int t0 = 0; t0 < NN; t0 += 128) {
        __syncthreads();
        #pragma unroll
        for (int g = 0; g < 4; g++) {
            const int j = tid + 128 * g;
            const int key = j >> 2, seg = j & 3;
            *(uint4*)(Ksm + key * 40 + seg * 8) = kg[(size_t)t0 * 4 + j];
        }
        #pragma unroll
        for (int g = 0; g < 2; g++) {
            const int j = tid + 128 * g;
            const int e = j >> 4, seg = j & 15;
            *(uint4*)(Vh + e * 136 + seg * 8) = *(const uint4*)(vhg + (size_t)e * NN + t0 + seg * 8);
        }
        __syncthreads();

        // ---- QK ----
        float S[2][16][4];
        #pragma unroll
        for (int m = 0; m < 2; m++)
            #pragma unroll
            for (int n = 0; n < 16; n++)
                #pragma unroll
                for (int i = 0; i < 4; i++) S[m][n][i] = 0.f;

        #pragma unroll
        for (int n = 0; n < 16; n++) {
            const __half* kb = Ksm + (n * 8 + lq) * 40 + lc * 2;
            const uint32_t bh0 = *(const uint32_t*)kb;
            const uint32_t bh1 = *(const uint32_t*)(kb + 8);
            const uint32_t bl0 = *(const uint32_t*)(kb + 16);
            const uint32_t bl1 = *(const uint32_t*)(kb + 24);
            #pragma unroll
            for (int m = 0; m < 2; m++) {
                mma_f16(S[m][n], qh[m], bh0, bh1);
                mma_f16(S[m][n], ql[m], bh0, bh1);
                mma_f16(S[m][n], qh[m], bl0, bl1);
            }
        }

        // ---- softmax (rows: lq + {0,8,16,24}) ----
        float cm[4] = {-1e30f, -1e30f, -1e30f, -1e30f};
        #pragma unroll
        for (int m = 0; m < 2; m++)
            #pragma unroll
            for (int n = 0; n < 16; n++) {
                cm[2*m]   = fmaxf(cm[2*m],   fmaxf(S[m][n][0], S[m][n][1]));
                cm[2*m+1] = fmaxf(cm[2*m+1], fmaxf(S[m][n][2], S[m][n][3]));
            }
        #pragma unroll
        for (int r = 0; r < 4; r++) {
            const float mn = fmaxf(mr[r], qmax(cm[r]));
            const float corr = ex2f_fast(mr[r] - mn);
            mr[r] = mn; lrow[r] *= corr;
            const int m = r >> 1, h2 = (r & 1) * 2;
            #pragma unroll
            for (int nb = 0; nb < 2; nb++) {
                o[m][nb][h2]   *= corr;
                o[m][nb][h2+1] *= corr;
            }
        }
        float rs[4] = {0.f, 0.f, 0.f, 0.f};
        #pragma unroll
        for (int m = 0; m < 2; m++)
            #pragma unroll
            for (int n = 0; n < 16; n++) {
                const float p0 = ex2f_fast(S[m][n][0] - mr[2*m]);
                const float p1 = ex2f_fast(S[m][n][1] - mr[2*m]);
                const float p2 = ex2f_fast(S[m][n][2] - mr[2*m+1]);
                const float p3 = ex2f_fast(S[m][n][3] - mr[2*m+1]);
                rs[2*m]   += p0 + p1;
                rs[2*m+1] += p2 + p3;
                S[m][n][0] = __uint_as_float(cvt_h2(p0, p1));  // keys (2lc, 2lc+1), row lq
                S[m][n][1] = __uint_as_float(cvt_h2(p2, p3));  // keys (2lc, 2lc+1), row lq+8
            }
        #pragma unroll
        for (int r = 0; r < 4; r++) lrow[r] += qsum(rs[r]);

        // ---- PV: o += Phi*V ----
        #pragma unroll
        for (int kb = 0; kb < 8; kb++) {
            #pragma unroll
            for (int nb = 0; nb < 2; nb++) {
                const __half* vb = Vh + (nb * 8 + lq) * 136 + kb * 16 + lc * 2;
                const uint32_t b0 = *(const uint32_t*)vb;
                const uint32_t b1 = *(const uint32_t*)(vb + 8);
                #pragma unroll
                for (int m = 0; m < 2; m++) {
                    const uint32_t ah[4] = {
                        __float_as_uint(S[m][2*kb][0]),   __float_as_uint(S[m][2*kb][1]),
                        __float_as_uint(S[m][2*kb+1][0]), __float_as_uint(S[m][2*kb+1][1])
                    };
                    mma_f16(o[m][nb], ah, b0, b1);
                }
            }
        }
    }

    // ---- epilogue ----
    float inv[4];
    #pragma unroll
    for (int r = 0; r < 4; r++) inv[r] = 1.0f / lrow[r];
    const int b = bh >> 3, hh = bh & 7;
    #pragma unroll
    for (int m = 0; m < 2; m++) {
        const int rA = qrow0 + m * 16 + lq;
        #pragma unroll
        for (int nb = 0; nb < 2; nb++) {
            const int e0 = nb * 8 + lc * 2;
            float* pA = g_ctx + ((size_t)(b * NN + rA)) * 128 + hh * 16 + e0;
            float* pB = pA + 8 * 128;
            *(float2*)pA = make_float2(o[m][nb][0] * inv[2*m],   o[m][nb][1] * inv[2*m]);
            *(float2*)pB = make_float2(o[m][nb][2] * inv[2*m+1], o[m][nb][3] * inv[2*m+1]);
        }
    }
}

// ---------------- output projection (32 rows/CTA, 2 outputs/thread) ----------------
__global__ void __launch_bounds__(256) outproj_kernel(
    const float* __restrict__ Wo, const float* __restrict__ bo,
    float* __restrict__ out)
{
    __shared__ float Cs[32][128];
    __shared__ float Ws[16][132];
    const int r0 = blockIdx.x * 32;
    const float4* cg = (const float4*)(g_ctx + ((size_t)r0 << 7));
    float4* csv = (float4*)&Cs[0][0];
    #pragma unroll
    for (int i = 0; i < 4; i++)
        csv[threadIdx.x + 256 * i] = cg[threadIdx.x + 256 * i];
    for (int i = threadIdx.x; i < 2048; i += 256) Ws[i >> 7][i & 127] = Wo[i];
    __syncthreads();
    const int r = threadIdx.x >> 4, c = threadIdx.x & 15;
    float acc0 = bo[c], acc1 = bo[c];
    #pragma unroll
    for (int kk = 0; kk < 128; kk += 4) {
        float4 w = *(const float4*)&Ws[c][kk];
        float4 a0 = *(const float4*)&Cs[r][kk];
        float4 a1 = *(const float4*)&Cs[r + 16][kk];
        acc0 = dot4acc(a0, w, acc0);
        acc1 = dot4acc(a1, w, acc1);
    }
    out[((size_t)(r0 + r) << 4) + c]      = acc0;
    out[((size_t)(r0 + r + 16) << 4) + c] = acc1;
}

// ---------------- launcher ----------------
extern "C" void kernel_launch(void* const* d_in, const int* in_sizes, int n_in,
                              void* d_out, int out_size)
{
    const float* query = (const float*)d_in[0];
    const float* key   = (const float*)d_in[1];
    const float* value = (const float*)d_in[2];
    const float* Wq    = (const float*)d_in[3];
    const float* bq    = (const float*)d_in[4];
    const float* Wk    = (const float*)d_in[5];
    const float* bk    = (const float*)d_in[6];
    const float* Wv    = (const float*)d_in[7];
    const float* bv    = (const float*)d_in[8];
    const float* Wo    = (const float*)d_in[9];
    const float* bo    = (const float*)d_in[10];
    float* out = (float*)d_out;

    const float alpha_q = 0.25f * 1.4426950408889634f;

    dim3 gqk(MROWS / 32, 2);
    projqk_kernel<<<gqk, 128>>>(query, key, Wq, Wk, bq, bk, alpha_q);
    projvt_kernel<<<BHN * 16, 128>>>(value, Wv, bv);
    attn_mma_kernel<<<BHN * 16, 128>>>();
    outproj_kernel<<<MROWS / 32, 256>>>(Wo, bo, out);
}